// round 1
// baseline (speedup 1.0000x reference)
#include <cuda_runtime.h>
#include <cuda_bf16.h>
#include <math.h>

// Problem constants (fixed by the dataset)
#define Bc    8
#define Nc    9856
#define Dc    256
#define HEADS 8
#define HD    32          // Dc / HEADS
#define WH    7
#define WW    11
#define L77   77          // WH*WW
#define HIDc  512
#define Hc    56
#define Wc    176
#define NH    8           // Hc/WH
#define NW    16          // Wc/WW
#define MROWS (Bc * Nc)   // 78848
#define NWIN  (Bc * NH * NW)  // 1024

// ---------------------------------------------------------------------------
// Scratch (device globals; allocation-free per harness rules)
// ---------------------------------------------------------------------------
__device__ float g_xn[(size_t)MROWS * Dc];            // LN1 output, later reused as attn output
__device__ float g_qkv[(size_t)MROWS * 3 * Dc];       // QKV; later reused as [yn | hmid]
__device__ float g_y[(size_t)MROWS * Dc];             // x + attn_out

// ---------------------------------------------------------------------------
// LayerNorm: one warp per row of 256
// ---------------------------------------------------------------------------
__global__ void __launch_bounds__(256) ln_kernel(const float* __restrict__ x,
                                                 const float* __restrict__ g,
                                                 const float* __restrict__ b,
                                                 float* __restrict__ out)
{
    int warp = threadIdx.x >> 5, lane = threadIdx.x & 31;
    size_t row = (size_t)blockIdx.x * 8 + warp;
    const float* xr = x + row * Dc;
    int c = lane * 8;
    float4 v0 = *(const float4*)(xr + c);
    float4 v1 = *(const float4*)(xr + c + 4);
    float sum = v0.x + v0.y + v0.z + v0.w + v1.x + v1.y + v1.z + v1.w;
    float sq  = v0.x*v0.x + v0.y*v0.y + v0.z*v0.z + v0.w*v0.w
              + v1.x*v1.x + v1.y*v1.y + v1.z*v1.z + v1.w*v1.w;
    #pragma unroll
    for (int off = 16; off; off >>= 1) {
        sum += __shfl_xor_sync(0xffffffff, sum, off);
        sq  += __shfl_xor_sync(0xffffffff, sq,  off);
    }
    float mu  = sum * (1.0f / 256.0f);
    float var = sq * (1.0f / 256.0f) - mu * mu;
    float rs  = rsqrtf(var + 1e-5f);
    float4 g0 = *(const float4*)(g + c), g1 = *(const float4*)(g + c + 4);
    float4 b0 = *(const float4*)(b + c), b1 = *(const float4*)(b + c + 4);
    float4 o0, o1;
    o0.x = (v0.x - mu) * rs * g0.x + b0.x;  o0.y = (v0.y - mu) * rs * g0.y + b0.y;
    o0.z = (v0.z - mu) * rs * g0.z + b0.z;  o0.w = (v0.w - mu) * rs * g0.w + b0.w;
    o1.x = (v1.x - mu) * rs * g1.x + b1.x;  o1.y = (v1.y - mu) * rs * g1.y + b1.y;
    o1.z = (v1.z - mu) * rs * g1.z + b1.z;  o1.w = (v1.w - mu) * rs * g1.w + b1.w;
    *(float4*)(out + row * Dc + c)     = o0;
    *(float4*)(out + row * Dc + c + 4) = o1;
}

// ---------------------------------------------------------------------------
// GEMM: C[M,N] = A[M,K] @ B[N,K]^T + bias[N]  (+ epilogue)
//   EPI 0: bias only   EPI 1: bias + exact GELU   EPI 2: bias + residual add
// 64x64 tile, BK=16, 256 threads, 4x4 per thread. M%64==0, N%64==0, K%16==0.
// ---------------------------------------------------------------------------
__device__ __forceinline__ float gelu_exact(float v)
{
    return 0.5f * v * (1.0f + erff(v * 0.70710678118654752f));
}

template <int EPI>
__global__ void __launch_bounds__(256) gemm_kernel(const float* __restrict__ A,
                                                   const float* __restrict__ B,
                                                   const float* __restrict__ bias,
                                                   const float* __restrict__ resid,
                                                   float* __restrict__ C,
                                                   int M, int N, int K)
{
    const int BM = 64, BN = 64, BK = 16;
    __shared__ float As[BK][BM];
    __shared__ float Bs[BK][BN];

    int tid = threadIdx.x;
    int tx = tid & 15, ty = tid >> 4;
    int m0 = blockIdx.y * BM, n0 = blockIdx.x * BN;

    int lrow = tid >> 2;        // 0..63
    int lcol = (tid & 3) << 2;  // 0,4,8,12

    const float* Aptr = A + (size_t)(m0 + lrow) * K + lcol;
    const float* Bptr = B + (size_t)(n0 + lrow) * K + lcol;

    float acc[4][4] = {};

    for (int kt = 0; kt < K; kt += BK) {
        float4 av = *(const float4*)(Aptr + kt);
        float4 bv = *(const float4*)(Bptr + kt);
        As[lcol + 0][lrow] = av.x;  As[lcol + 1][lrow] = av.y;
        As[lcol + 2][lrow] = av.z;  As[lcol + 3][lrow] = av.w;
        Bs[lcol + 0][lrow] = bv.x;  Bs[lcol + 1][lrow] = bv.y;
        Bs[lcol + 2][lrow] = bv.z;  Bs[lcol + 3][lrow] = bv.w;
        __syncthreads();
        #pragma unroll
        for (int kk = 0; kk < BK; kk++) {
            float4 a = *(const float4*)&As[kk][ty << 2];
            float4 b = *(const float4*)&Bs[kk][tx << 2];
            float ar[4] = {a.x, a.y, a.z, a.w};
            float br[4] = {b.x, b.y, b.z, b.w};
            #pragma unroll
            for (int i = 0; i < 4; i++)
                #pragma unroll
                for (int j = 0; j < 4; j++)
                    acc[i][j] += ar[i] * br[j];
        }
        __syncthreads();
    }

    float4 bb = *(const float4*)&bias[n0 + (tx << 2)];
    float bbr[4] = {bb.x, bb.y, bb.z, bb.w};
    #pragma unroll
    for (int i = 0; i < 4; i++) {
        size_t m = (size_t)m0 + (ty << 2) + i;
        float c[4];
        #pragma unroll
        for (int j = 0; j < 4; j++) {
            float v = acc[i][j] + bbr[j];
            if (EPI == 1) v = gelu_exact(v);
            c[j] = v;
        }
        if (EPI == 2) {
            float4 r = *(const float4*)&resid[m * N + n0 + (tx << 2)];
            c[0] += r.x; c[1] += r.y; c[2] += r.z; c[3] += r.w;
        }
        float4 cv = make_float4(c[0], c[1], c[2], c[3]);
        *(float4*)&C[m * N + n0 + (tx << 2)] = cv;
    }
}

// ---------------------------------------------------------------------------
// Windowed attention: one CTA per (window, head). 77 tokens, hd=32.
// Gathers QKV rows via the window-partition permutation, scatters O back.
// ---------------------------------------------------------------------------
__device__ __forceinline__ int rowmap(int wi, int l)
{
    int b   = wi >> 7;        // / (NH*NW) = /128
    int rem = wi & 127;
    int hb  = rem >> 4;       // / NW(=16)
    int wb  = rem & 15;
    int r   = l / WW;
    int c   = l - r * WW;
    return b * Nc + (hb * WH + r) * Wc + wb * WW + c;
}

__global__ void __launch_bounds__(256) attn_kernel(const float* __restrict__ qkv,
                                                   float* __restrict__ o)
{
    __shared__ float sQ[L77 * 33];
    __shared__ float sK[L77 * 33];
    __shared__ float sV[L77 * 33];
    __shared__ float sP[8][80];

    int bx = blockIdx.x;
    int wi = bx >> 3, h = bx & 7;
    int tid = threadIdx.x, lane = tid & 31, w = tid >> 5;

    for (int idx = tid; idx < L77 * HD; idx += 256) {
        int l = idx >> 5, d = idx & 31;
        int grow = rowmap(wi, l);
        const float* base = qkv + (size_t)grow * (3 * Dc) + h * HD + d;
        sQ[l * 33 + d] = base[0];
        sK[l * 33 + d] = base[Dc];
        sV[l * 33 + d] = base[2 * Dc];
    }
    __syncthreads();

    const float scale = 0.17677669529663687f;  // 1/sqrt(32)
    int j2 = lane + 64;
    bool v2 = (j2 < L77);

    for (int i = w; i < L77; i += 8) {
        float s0 = 0.f, s1 = 0.f, s2 = 0.f;
        #pragma unroll 8
        for (int d = 0; d < HD; d++) {
            float qd = sQ[i * 33 + d];
            s0 += qd * sK[lane * 33 + d];
            s1 += qd * sK[(lane + 32) * 33 + d];
            if (v2) s2 += qd * sK[j2 * 33 + d];
        }
        s0 *= scale; s1 *= scale;
        s2 = v2 ? s2 * scale : -1e30f;
        float mx = fmaxf(s0, fmaxf(s1, s2));
        #pragma unroll
        for (int off = 16; off; off >>= 1)
            mx = fmaxf(mx, __shfl_xor_sync(0xffffffff, mx, off));
        float e0 = __expf(s0 - mx), e1 = __expf(s1 - mx);
        float e2 = v2 ? __expf(s2 - mx) : 0.f;
        float sum = e0 + e1 + e2;
        #pragma unroll
        for (int off = 16; off; off >>= 1)
            sum += __shfl_xor_sync(0xffffffff, sum, off);
        float inv = 1.0f / sum;
        sP[w][lane]      = e0 * inv;
        sP[w][lane + 32] = e1 * inv;
        if (v2) sP[w][j2] = e2 * inv;
        __syncwarp();
        float acc = 0.f;
        #pragma unroll 7
        for (int j = 0; j < L77; j++)
            acc += sP[w][j] * sV[j * 33 + lane];
        int grow = rowmap(wi, i);
        o[(size_t)grow * Dc + h * HD + lane] = acc;
        __syncwarp();
    }
}

// ---------------------------------------------------------------------------
// Launch
// ---------------------------------------------------------------------------
extern "C" void kernel_launch(void* const* d_in, const int* in_sizes, int n_in,
                              void* d_out, int out_size)
{
    const float* x        = (const float*)d_in[0];
    const float* norm1_g  = (const float*)d_in[1];
    const float* norm1_b  = (const float*)d_in[2];
    const float* in_proj_w = (const float*)d_in[3];
    const float* in_proj_b = (const float*)d_in[4];
    const float* out_w    = (const float*)d_in[5];
    const float* out_b    = (const float*)d_in[6];
    const float* norm2_g  = (const float*)d_in[7];
    const float* norm2_b  = (const float*)d_in[8];
    const float* fc1_w    = (const float*)d_in[9];
    const float* fc1_b    = (const float*)d_in[10];
    const float* fc2_w    = (const float*)d_in[11];
    const float* fc2_b    = (const float*)d_in[12];
    float* out = (float*)d_out;

    float *p_xn, *p_qkv, *p_y;
    cudaGetSymbolAddress((void**)&p_xn,  g_xn);
    cudaGetSymbolAddress((void**)&p_qkv, g_qkv);
    cudaGetSymbolAddress((void**)&p_y,   g_y);

    // 1) LN1: x -> xn
    ln_kernel<<<MROWS / 8, 256>>>(x, norm1_g, norm1_b, p_xn);

    // 2) QKV: xn @ in_proj_w^T + b  -> qkv  [M x 768]
    {
        dim3 grid(768 / 64, MROWS / 64);
        gemm_kernel<0><<<grid, 256>>>(p_xn, in_proj_w, in_proj_b, nullptr,
                                      p_qkv, MROWS, 3 * Dc, Dc);
    }

    // 3) Windowed attention: qkv -> o (reuse g_xn)
    attn_kernel<<<NWIN * HEADS, 256>>>(p_qkv, p_xn);

    // 4) out proj + residual: y = x + o @ out_w^T + out_b
    {
        dim3 grid(Dc / 64, MROWS / 64);
        gemm_kernel<2><<<grid, 256>>>(p_xn, out_w, out_b, x, p_y,
                                      MROWS, Dc, Dc);
    }

    // 5) LN2: y -> yn (store in g_qkv[0 : M*256))
    ln_kernel<<<MROWS / 8, 256>>>(p_y, norm2_g, norm2_b, p_qkv);

    // 6) FC1 + GELU: hmid = gelu(yn @ fc1_w^T + fc1_b)  (store at g_qkv + M*256)
    float* p_yn   = p_qkv;
    float* p_hmid = p_qkv + (size_t)MROWS * Dc;
    {
        dim3 grid(HIDc / 64, MROWS / 64);
        gemm_kernel<1><<<grid, 256>>>(p_yn, fc1_w, fc1_b, nullptr, p_hmid,
                                      MROWS, HIDc, Dc);
    }

    // 7) FC2 + residual: out = y + hmid @ fc2_w^T + fc2_b
    {
        dim3 grid(Dc / 64, MROWS / 64);
        gemm_kernel<2><<<grid, 256>>>(p_hmid, fc2_w, fc2_b, p_y, out,
                                      MROWS, Dc, HIDc);
    }
}

// round 2
// speedup vs baseline: 2.4630x; 2.4630x over previous
#include <cuda_runtime.h>
#include <cuda_bf16.h>
#include <math.h>

// Problem constants (fixed by the dataset)
#define Bc    8
#define Nc    9856
#define Dc    256
#define HEADS 8
#define HD    32
#define WH    7
#define WW    11
#define L77   77
#define HIDc  512
#define Hc    56
#define Wc    176
#define NH    8
#define NWn   16
#define MROWS (Bc * Nc)       // 78848
#define NWIN  (Bc * NH * NWn) // 1024

// ---------------------------------------------------------------------------
// Scratch
// ---------------------------------------------------------------------------
__device__ float g_xn[(size_t)MROWS * Dc];
__device__ float g_qkv[(size_t)MROWS * 3 * Dc];   // later reused as [yn | hmid]
__device__ float g_y[(size_t)MROWS * Dc];

// ---------------------------------------------------------------------------
// LayerNorm: one warp per row of 256
// ---------------------------------------------------------------------------
__global__ void __launch_bounds__(256) ln_kernel(const float* __restrict__ x,
                                                 const float* __restrict__ g,
                                                 const float* __restrict__ b,
                                                 float* __restrict__ out)
{
    int warp = threadIdx.x >> 5, lane = threadIdx.x & 31;
    size_t row = (size_t)blockIdx.x * 8 + warp;
    const float* xr = x + row * Dc;
    int c = lane * 8;
    float4 v0 = *(const float4*)(xr + c);
    float4 v1 = *(const float4*)(xr + c + 4);
    float sum = v0.x + v0.y + v0.z + v0.w + v1.x + v1.y + v1.z + v1.w;
    float sq  = v0.x*v0.x + v0.y*v0.y + v0.z*v0.z + v0.w*v0.w
              + v1.x*v1.x + v1.y*v1.y + v1.z*v1.z + v1.w*v1.w;
    #pragma unroll
    for (int off = 16; off; off >>= 1) {
        sum += __shfl_xor_sync(0xffffffff, sum, off);
        sq  += __shfl_xor_sync(0xffffffff, sq,  off);
    }
    float mu  = sum * (1.0f / 256.0f);
    float var = sq * (1.0f / 256.0f) - mu * mu;
    float rs  = rsqrtf(var + 1e-5f);
    float4 g0 = *(const float4*)(g + c), g1 = *(const float4*)(g + c + 4);
    float4 b0 = *(const float4*)(b + c), b1 = *(const float4*)(b + c + 4);
    float4 o0, o1;
    o0.x = (v0.x - mu) * rs * g0.x + b0.x;  o0.y = (v0.y - mu) * rs * g0.y + b0.y;
    o0.z = (v0.z - mu) * rs * g0.z + b0.z;  o0.w = (v0.w - mu) * rs * g0.w + b0.w;
    o1.x = (v1.x - mu) * rs * g1.x + b1.x;  o1.y = (v1.y - mu) * rs * g1.y + b1.y;
    o1.z = (v1.z - mu) * rs * g1.z + b1.z;  o1.w = (v1.w - mu) * rs * g1.w + b1.w;
    *(float4*)(out + row * Dc + c)     = o0;
    *(float4*)(out + row * Dc + c + 4) = o1;
}

// ---------------------------------------------------------------------------
// tf32 tensor-core GEMM: C[M,N] = A[M,K] @ B[N,K]^T + bias (+epilogue)
// CTA tile 128x128, BK=16, 8 warps, warp tile 64x32 (4x4 m16n8k8 mma).
// EPI 0: bias; 1: bias+GELU; 2: bias+residual
// ---------------------------------------------------------------------------
__device__ __forceinline__ unsigned f2tf32(float f)
{
    unsigned r;
    asm("cvt.rna.tf32.f32 %0, %1;" : "=r"(r) : "f"(f));
    return r;
}

__device__ __forceinline__ void mma_tf32(float (&c)[4], const unsigned (&a)[4],
                                         const unsigned (&b)[2])
{
    asm volatile(
        "mma.sync.aligned.m16n8k8.row.col.f32.tf32.tf32.f32 "
        "{%0,%1,%2,%3}, {%4,%5,%6,%7}, {%8,%9}, {%0,%1,%2,%3};"
        : "+f"(c[0]), "+f"(c[1]), "+f"(c[2]), "+f"(c[3])
        : "r"(a[0]), "r"(a[1]), "r"(a[2]), "r"(a[3]), "r"(b[0]), "r"(b[1]));
}

__device__ __forceinline__ float gelu_exact(float v)
{
    return 0.5f * v * (1.0f + erff(v * 0.70710678118654752f));
}

template <int EPI>
__global__ void __launch_bounds__(256) tgemm_kernel(const float* __restrict__ A,
                                                    const float* __restrict__ B,
                                                    const float* __restrict__ bias,
                                                    const float* __restrict__ resid,
                                                    float* __restrict__ C,
                                                    int M, int N, int K)
{
    __shared__ unsigned As[128][20];  // [m][k], pitch 20 -> conflict-free frag loads
    __shared__ unsigned Bs[128][20];  // [n][k]

    int tid  = threadIdx.x;
    int lane = tid & 31, warp = tid >> 5;
    int wm = warp >> 2, wn = warp & 3;       // 2 x 4 warp grid
    int g = lane >> 2, t = lane & 3;
    int m0 = blockIdx.y * 128, n0 = blockIdx.x * 128;

    float acc[4][4][4] = {};

    int lr = tid >> 2;           // 0..63
    int lc = (tid & 3) << 2;     // 0,4,8,12
    const float* Ag0 = A + (size_t)(m0 + lr) * K + lc;
    const float* Ag1 = Ag0 + (size_t)64 * K;
    const float* Bg0 = B + (size_t)(n0 + lr) * K + lc;
    const float* Bg1 = Bg0 + (size_t)64 * K;

    for (int kt = 0; kt < K; kt += 16) {
        float4 av0 = *(const float4*)(Ag0 + kt);
        float4 av1 = *(const float4*)(Ag1 + kt);
        float4 bv0 = *(const float4*)(Bg0 + kt);
        float4 bv1 = *(const float4*)(Bg1 + kt);
        __syncthreads();
        As[lr][lc+0] = f2tf32(av0.x); As[lr][lc+1] = f2tf32(av0.y);
        As[lr][lc+2] = f2tf32(av0.z); As[lr][lc+3] = f2tf32(av0.w);
        As[lr+64][lc+0] = f2tf32(av1.x); As[lr+64][lc+1] = f2tf32(av1.y);
        As[lr+64][lc+2] = f2tf32(av1.z); As[lr+64][lc+3] = f2tf32(av1.w);
        Bs[lr][lc+0] = f2tf32(bv0.x); Bs[lr][lc+1] = f2tf32(bv0.y);
        Bs[lr][lc+2] = f2tf32(bv0.z); Bs[lr][lc+3] = f2tf32(bv0.w);
        Bs[lr+64][lc+0] = f2tf32(bv1.x); Bs[lr+64][lc+1] = f2tf32(bv1.y);
        Bs[lr+64][lc+2] = f2tf32(bv1.z); Bs[lr+64][lc+3] = f2tf32(bv1.w);
        __syncthreads();

        #pragma unroll
        for (int kk = 0; kk < 16; kk += 8) {
            unsigned af[4][4], bf[4][2];
            #pragma unroll
            for (int mt = 0; mt < 4; mt++) {
                int row = wm * 64 + mt * 16;
                af[mt][0] = As[row + g    ][kk + t];
                af[mt][1] = As[row + g + 8][kk + t];
                af[mt][2] = As[row + g    ][kk + t + 4];
                af[mt][3] = As[row + g + 8][kk + t + 4];
            }
            #pragma unroll
            for (int nt = 0; nt < 4; nt++) {
                int col = wn * 32 + nt * 8;
                bf[nt][0] = Bs[col + g][kk + t];
                bf[nt][1] = Bs[col + g][kk + t + 4];
            }
            #pragma unroll
            for (int mt = 0; mt < 4; mt++)
                #pragma unroll
                for (int nt = 0; nt < 4; nt++)
                    mma_tf32(acc[mt][nt], af[mt], bf[nt]);
        }
    }

    // Epilogue: c0,c1 -> (row g, cols 2t,2t+1); c2,c3 -> (row g+8)
    #pragma unroll
    for (int mt = 0; mt < 4; mt++) {
        size_t r0 = (size_t)m0 + wm * 64 + mt * 16 + g;
        size_t r1 = r0 + 8;
        #pragma unroll
        for (int nt = 0; nt < 4; nt++) {
            int col = n0 + wn * 32 + nt * 8 + 2 * t;
            float b0 = bias[col], b1 = bias[col + 1];
            float v00 = acc[mt][nt][0] + b0, v01 = acc[mt][nt][1] + b1;
            float v10 = acc[mt][nt][2] + b0, v11 = acc[mt][nt][3] + b1;
            if (EPI == 1) {
                v00 = gelu_exact(v00); v01 = gelu_exact(v01);
                v10 = gelu_exact(v10); v11 = gelu_exact(v11);
            }
            if (EPI == 2) {
                float2 q0 = *(const float2*)&resid[r0 * N + col];
                float2 q1 = *(const float2*)&resid[r1 * N + col];
                v00 += q0.x; v01 += q0.y; v10 += q1.x; v11 += q1.y;
            }
            *(float2*)&C[r0 * N + col] = make_float2(v00, v01);
            *(float2*)&C[r1 * N + col] = make_float2(v10, v11);
        }
    }
}

// ---------------------------------------------------------------------------
// Windowed attention: one CTA per (window, head). Each warp does 2 query
// rows per pass (K/V smem traffic amortized), float4 K reads, pitch 36.
// ---------------------------------------------------------------------------
__device__ __forceinline__ int rowmap(int wi, int l)
{
    int b   = wi >> 7;
    int rem = wi & 127;
    int hb  = rem >> 4;
    int wb  = rem & 15;
    int r   = l / WW;
    int c   = l - r * WW;
    return b * Nc + (hb * WH + r) * Wc + wb * WW + c;
}

__global__ void __launch_bounds__(256) attn_kernel(const float* __restrict__ qkv,
                                                   float* __restrict__ o)
{
    __shared__ float sQ[L77 * 36];
    __shared__ float sK[L77 * 36];
    __shared__ float sV[L77 * 36];
    __shared__ float sP[16][80];

    int bx = blockIdx.x;
    int wi = bx >> 3, h = bx & 7;
    int tid = threadIdx.x, lane = tid & 31, w = tid >> 5;

    for (int idx = tid; idx < L77 * HD; idx += 256) {
        int l = idx >> 5, d = idx & 31;
        int grow = rowmap(wi, l);
        const float* base = qkv + (size_t)grow * (3 * Dc) + h * HD + d;
        sQ[l * 36 + d] = base[0];
        sK[l * 36 + d] = base[Dc];
        sV[l * 36 + d] = base[2 * Dc];
    }
    __syncthreads();

    const float scale = 0.17677669529663687f;  // 1/sqrt(32)
    bool v2 = (lane < 13);                     // lane+64 < 77
    int pr = w * 2;

    for (int r = 0; r < 5; r++) {
        int ia = 2 * w + 16 * r;
        if (ia >= L77) break;
        bool hb = (ia + 1 < L77);
        int ib = hb ? ia + 1 : ia;

        const float4* qa4 = (const float4*)&sQ[ia * 36];
        const float4* qb4 = (const float4*)&sQ[ib * 36];

        float sa0 = 0.f, sa1 = 0.f, sa2 = 0.f;
        float sb0 = 0.f, sb1 = 0.f, sb2 = 0.f;
        #pragma unroll
        for (int d4 = 0; d4 < 8; d4++) {
            float4 k0 = *(const float4*)&sK[lane * 36 + d4 * 4];
            float4 k1 = *(const float4*)&sK[(lane + 32) * 36 + d4 * 4];
            float4 qa = qa4[d4];
            float4 qb = qb4[d4];
            sa0 += qa.x*k0.x + qa.y*k0.y + qa.z*k0.z + qa.w*k0.w;
            sa1 += qa.x*k1.x + qa.y*k1.y + qa.z*k1.z + qa.w*k1.w;
            sb0 += qb.x*k0.x + qb.y*k0.y + qb.z*k0.z + qb.w*k0.w;
            sb1 += qb.x*k1.x + qb.y*k1.y + qb.z*k1.z + qb.w*k1.w;
            if (v2) {
                float4 k2 = *(const float4*)&sK[(lane + 64) * 36 + d4 * 4];
                sa2 += qa.x*k2.x + qa.y*k2.y + qa.z*k2.z + qa.w*k2.w;
                sb2 += qb.x*k2.x + qb.y*k2.y + qb.z*k2.z + qb.w*k2.w;
            }
        }
        sa0 *= scale; sa1 *= scale; sb0 *= scale; sb1 *= scale;
        sa2 = v2 ? sa2 * scale : -1e30f;
        sb2 = v2 ? sb2 * scale : -1e30f;

        // softmax row a
        float mxa = fmaxf(sa0, fmaxf(sa1, sa2));
        float mxb = fmaxf(sb0, fmaxf(sb1, sb2));
        #pragma unroll
        for (int off = 16; off; off >>= 1) {
            mxa = fmaxf(mxa, __shfl_xor_sync(0xffffffff, mxa, off));
            mxb = fmaxf(mxb, __shfl_xor_sync(0xffffffff, mxb, off));
        }
        float ea0 = __expf(sa0 - mxa), ea1 = __expf(sa1 - mxa);
        float ea2 = v2 ? __expf(sa2 - mxa) : 0.f;
        float eb0 = __expf(sb0 - mxb), eb1 = __expf(sb1 - mxb);
        float eb2 = v2 ? __expf(sb2 - mxb) : 0.f;
        float suma = ea0 + ea1 + ea2;
        float sumb = eb0 + eb1 + eb2;
        #pragma unroll
        for (int off = 16; off; off >>= 1) {
            suma += __shfl_xor_sync(0xffffffff, suma, off);
            sumb += __shfl_xor_sync(0xffffffff, sumb, off);
        }
        float inva = 1.0f / suma, invb = 1.0f / sumb;
        sP[pr][lane]      = ea0 * inva;
        sP[pr][lane + 32] = ea1 * inva;
        if (v2) sP[pr][lane + 64] = ea2 * inva;
        sP[pr + 1][lane]      = eb0 * invb;
        sP[pr + 1][lane + 32] = eb1 * invb;
        if (v2) sP[pr + 1][lane + 64] = eb2 * invb;
        __syncwarp();

        float acca = 0.f, accb = 0.f;
        #pragma unroll 7
        for (int j = 0; j < L77; j++) {
            float vv = sV[j * 36 + lane];
            acca += sP[pr][j] * vv;
            accb += sP[pr + 1][j] * vv;
        }
        int growa = rowmap(wi, ia);
        o[(size_t)growa * Dc + h * HD + lane] = acca;
        if (hb) {
            int growb = rowmap(wi, ib);
            o[(size_t)growb * Dc + h * HD + lane] = accb;
        }
        __syncwarp();
    }
}

// ---------------------------------------------------------------------------
// Launch
// ---------------------------------------------------------------------------
extern "C" void kernel_launch(void* const* d_in, const int* in_sizes, int n_in,
                              void* d_out, int out_size)
{
    const float* x         = (const float*)d_in[0];
    const float* norm1_g   = (const float*)d_in[1];
    const float* norm1_b   = (const float*)d_in[2];
    const float* in_proj_w = (const float*)d_in[3];
    const float* in_proj_b = (const float*)d_in[4];
    const float* out_w     = (const float*)d_in[5];
    const float* out_b     = (const float*)d_in[6];
    const float* norm2_g   = (const float*)d_in[7];
    const float* norm2_b   = (const float*)d_in[8];
    const float* fc1_w     = (const float*)d_in[9];
    const float* fc1_b     = (const float*)d_in[10];
    const float* fc2_w     = (const float*)d_in[11];
    const float* fc2_b     = (const float*)d_in[12];
    float* out = (float*)d_out;

    float *p_xn, *p_qkv, *p_y;
    cudaGetSymbolAddress((void**)&p_xn,  g_xn);
    cudaGetSymbolAddress((void**)&p_qkv, g_qkv);
    cudaGetSymbolAddress((void**)&p_y,   g_y);

    // 1) LN1
    ln_kernel<<<MROWS / 8, 256>>>(x, norm1_g, norm1_b, p_xn);

    // 2) QKV = xn @ in_proj_w^T + b
    {
        dim3 grid(768 / 128, MROWS / 128);
        tgemm_kernel<0><<<grid, 256>>>(p_xn, in_proj_w, in_proj_b, nullptr,
                                       p_qkv, MROWS, 3 * Dc, Dc);
    }

    // 3) attention -> o (reuse g_xn)
    attn_kernel<<<NWIN * HEADS, 256>>>(p_qkv, p_xn);

    // 4) y = x + o @ out_w^T + out_b
    {
        dim3 grid(Dc / 128, MROWS / 128);
        tgemm_kernel<2><<<grid, 256>>>(p_xn, out_w, out_b, x, p_y,
                                       MROWS, Dc, Dc);
    }

    // 5) LN2: y -> yn (in g_qkv[0:M*256))
    ln_kernel<<<MROWS / 8, 256>>>(p_y, norm2_g, norm2_b, p_qkv);

    // 6) hmid = gelu(yn @ fc1_w^T + fc1_b)
    float* p_yn   = p_qkv;
    float* p_hmid = p_qkv + (size_t)MROWS * Dc;
    {
        dim3 grid(HIDc / 128, MROWS / 128);
        tgemm_kernel<1><<<grid, 256>>>(p_yn, fc1_w, fc1_b, nullptr, p_hmid,
                                       MROWS, HIDc, Dc);
    }

    // 7) out = y + hmid @ fc2_w^T + fc2_b
    {
        dim3 grid(Dc / 128, MROWS / 128);
        tgemm_kernel<2><<<grid, 256>>>(p_hmid, fc2_w, fc2_b, p_y, out,
                                       MROWS, Dc, HIDc);
    }
}